// round 1
// baseline (speedup 1.0000x reference)
#include <cuda_runtime.h>
#include <cuda_fp16.h>
#include <cstdint>

#define HH 512
#define WW 512
#define BATCH 32
#define WPR 16                       // uint32 words per row (512 bits)
#define WORDS_PER_IMG (HH * WPR)     // 8192 words = 32KB
#define TILE_H 32
#define GRAY_ROWS (TILE_H + 4)       // 36
#define MAG_ROWS  (TILE_H + 2)       // 34
#define MAG_PITCH (WW + 2)           // 514 (zero cols at 0 and 513)

// ---------------- device scratch (no allocations allowed) ----------------
__device__ uint32_t g_weak  [2 * BATCH * WORDS_PER_IMG];
__device__ uint32_t g_strong[2 * BATCH * WORDS_PER_IMG];
__device__ uint32_t g_edges [2 * BATCH * WORDS_PER_IMG];
__device__ unsigned int g_count;

__global__ void k_init() { g_count = 0u; }

// ---------------- fused gray -> sobel -> NMS -> threshold -> bitpack ------
__global__ __launch_bounds__(256) void k_frontend(const float* __restrict__ A,
                                                  const float* __restrict__ B) {
    extern __shared__ __half smemh[];
    __half* sg = smemh;                       // [GRAY_ROWS][WW]
    __half* sm = smemh + GRAY_ROWS * WW;      // [MAG_ROWS][MAG_PITCH]

    const int tid  = threadIdx.x;
    const int tile = blockIdx.x;
    const int b    = blockIdx.y;
    const int im   = blockIdx.z;
    const int r0   = tile * TILE_H;
    const float* img = (im == 0 ? A : B) + (size_t)b * 3 * HH * WW;

    // Stage 1: quantized grayscale with reflect rows (halo 2)
    for (int idx = tid; idx < GRAY_ROWS * WW; idx += 256) {
        int rr = idx >> 9, c = idx & (WW - 1);
        int gr = r0 - 2 + rr;
        gr = gr < 0 ? -gr : (gr > HH - 1 ? 2 * (HH - 1) - gr : gr);
        const float* p = img + gr * WW + c;
        float r = p[0], g = p[HH * WW], bl = p[2 * HH * WW];
        // match XLA: ((0.299*R + 0.587*G) + 0.114*B), each op separately rounded
        float v = __fadd_rn(__fadd_rn(__fmul_rn(0.299f, r), __fmul_rn(0.587f, g)),
                            __fmul_rn(0.114f, bl));
        v = floorf(__fmul_rn(v, 255.0f));
        v = fminf(fmaxf(v, 0.0f), 255.0f);     // exact integer 0..255
        sg[idx] = __float2half_rn(v);          // exact in fp16
    }
    __syncthreads();

    // Stage 2: |gx|+|gy| magnitude (reflect cols), zero outside the image
    for (int idx = tid; idx < MAG_ROWS * WW; idx += 256) {
        int rr = idx >> 9, c = idx & (WW - 1);
        int gr = r0 - 1 + rr;
        float m = 0.0f;
        if (gr >= 0 && gr < HH) {
            int sr = rr + 1;                   // gray smem row for global row gr
            int cm = (c == 0) ? 1 : c - 1;
            int cp = (c == WW - 1) ? WW - 2 : c + 1;
            float a00 = __half2float(sg[(sr - 1) * WW + cm]);
            float a01 = __half2float(sg[(sr - 1) * WW + c ]);
            float a02 = __half2float(sg[(sr - 1) * WW + cp]);
            float a10 = __half2float(sg[ sr      * WW + cm]);
            float a12 = __half2float(sg[ sr      * WW + cp]);
            float a20 = __half2float(sg[(sr + 1) * WW + cm]);
            float a21 = __half2float(sg[(sr + 1) * WW + c ]);
            float a22 = __half2float(sg[(sr + 1) * WW + cp]);
            float gx = (a02 - a00) + 2.0f * (a12 - a10) + (a22 - a20);
            float gy = (a20 + 2.0f * a21 + a22) - (a00 + 2.0f * a01 + a02);
            m = fabsf(gx) + fabsf(gy);         // exact integer <= 4080 (fits fp16 up to 2048? max is 2040+2040)
            // |gx|<=1020, |gy|<=1020 -> m<=2040, exact in fp16
        }
        sm[rr * MAG_PITCH + c + 1] = __float2half_rn(m);
    }
    for (int rr = tid; rr < MAG_ROWS; rr += 256) {
        sm[rr * MAG_PITCH + 0]      = __float2half_rn(0.0f);
        sm[rr * MAG_PITCH + WW + 1] = __float2half_rn(0.0f);
    }
    __syncthreads();

    // Stage 3: NMS + double threshold + ballot bitpack
    const int wid = tid >> 5, lane = tid & 31;
    const size_t obase = ((size_t)(im * BATCH + b)) * WORDS_PER_IMG;
#define SMV(r_, c_) __half2float(sm[(r_) * MAG_PITCH + (c_) + 1])
    for (int t = wid; t < TILE_H * WPR; t += 8) {
        int rr = t >> 4, word = t & 15;
        int c = word * 32 + lane;
        int sr = rr + 2;                        // gray smem row for output row
        int cm = (c == 0) ? 1 : c - 1;
        int cp = (c == WW - 1) ? WW - 2 : c + 1;
        float a00 = __half2float(sg[(sr - 1) * WW + cm]);
        float a01 = __half2float(sg[(sr - 1) * WW + c ]);
        float a02 = __half2float(sg[(sr - 1) * WW + cp]);
        float a10 = __half2float(sg[ sr      * WW + cm]);
        float a12 = __half2float(sg[ sr      * WW + cp]);
        float a20 = __half2float(sg[(sr + 1) * WW + cm]);
        float a21 = __half2float(sg[(sr + 1) * WW + c ]);
        float a22 = __half2float(sg[(sr + 1) * WW + cp]);
        float gx = (a02 - a00) + 2.0f * (a12 - a10) + (a22 - a20);
        float gy = (a20 + 2.0f * a21 + a22) - (a00 + 2.0f * a01 + a02);
        float ax = fabsf(gx), ay = fabsf(gy);
        float mag = ax + ay;
        float mW  = SMV(rr + 1, c - 1), mE  = SMV(rr + 1, c + 1);
        float mN  = SMV(rr,     c    ), mS  = SMV(rr + 2, c    );
        float mNW = SMV(rr,     c - 1), mSE = SMV(rr + 2, c + 1);
        float mNE = SMV(rr,     c + 1), mSW = SMV(rr + 2, c - 1);
        bool horiz = ay <= __fmul_rn((float)0.4142135623730951, ax);
        bool vert  = ay >= __fmul_rn((float)2.414213562373095,  ax);
        bool ss    = __fmul_rn(gx, gy) >= 0.0f;
        bool keep;
        if (horiz)      keep = (mag > mW)  & (mag >= mE);
        else if (vert)  keep = (mag > mN)  & (mag >= mS);
        else if (ss)    keep = (mag > mNW) & (mag >= mSE);
        else            keep = (mag > mNE) & (mag >= mSW);
        bool wk = keep && (mag > 25.0f);
        bool st = keep && (mag > 76.0f);
        unsigned wb = __ballot_sync(0xffffffffu, wk);
        unsigned sb = __ballot_sync(0xffffffffu, st);
        if (lane == 0) {
            g_weak  [obase + (size_t)(r0 + rr) * WPR + word] = wb;
            g_strong[obase + (size_t)(r0 + rr) * WPR + word] = sb;
        }
    }
#undef SMV
}

// ---------------- bitwise hysteresis (one CTA per (image,batch)) ----------
__device__ __forceinline__ void load_row16(const uint32_t* p, uint32_t* v) {
    const uint4* q = (const uint4*)p;
    uint4 a = q[0], b = q[1], c = q[2], d = q[3];
    v[0]=a.x; v[1]=a.y; v[2]=a.z; v[3]=a.w;
    v[4]=b.x; v[5]=b.y; v[6]=b.z; v[7]=b.w;
    v[8]=c.x; v[9]=c.y; v[10]=c.z; v[11]=c.w;
    v[12]=d.x; v[13]=d.y; v[14]=d.z; v[15]=d.w;
}
__device__ __forceinline__ void hdil_or(const uint32_t* v, uint32_t* acc) {
#pragma unroll
    for (int i = 0; i < WPR; i++) {
        uint32_t h = v[i] | (v[i] << 1) | (v[i] >> 1);
        if (i > 0)       h |= v[i - 1] >> 31;
        if (i < WPR - 1) h |= v[i + 1] << 31;
        acc[i] |= h;
    }
}

__global__ __launch_bounds__(256) void k_hyster() {
    extern __shared__ uint32_t s[];
    uint32_t* sw   = s;
    uint32_t* sst  = s + WORDS_PER_IMG;
    uint32_t* bufA = s + 2 * WORDS_PER_IMG;
    uint32_t* bufB = s + 3 * WORDS_PER_IMG;
    const int tid = threadIdx.x;
    const int im  = blockIdx.x >> 5, b = blockIdx.x & 31;
    const size_t base = ((size_t)(im * BATCH + b)) * WORDS_PER_IMG;

    for (int i = tid; i < WORDS_PER_IMG; i += 256) {
        uint32_t w  = g_weak[base + i];
        uint32_t st = g_strong[base + i];
        sw[i] = w; sst[i] = st; bufA[i] = st;
    }
    __syncthreads();

    uint32_t* cur = bufA;
    uint32_t* nxt = bufB;
    for (int it = 0; it < 64; ++it) {
        int changed = 0;
        for (int r = tid; r < HH; r += 256) {
            uint32_t cv[WPR], acc[WPR];
            load_row16(cur + r * WPR, cv);
#pragma unroll
            for (int i = 0; i < WPR; i++) acc[i] = 0u;
            hdil_or(cv, acc);
            if (r > 0) {
                uint32_t rv[WPR];
                load_row16(cur + (r - 1) * WPR, rv);
                hdil_or(rv, acc);
            }
            if (r < HH - 1) {
                uint32_t rv[WPR];
                load_row16(cur + (r + 1) * WPR, rv);
                hdil_or(rv, acc);
            }
            uint32_t wk[WPR], st[WPR];
            load_row16(sw  + r * WPR, wk);
            load_row16(sst + r * WPR, st);
            uint32_t out[WPR];
            uint32_t ch = 0;
#pragma unroll
            for (int i = 0; i < WPR; i++) {
                uint32_t nv = (acc[i] & wk[i]) | st[i];
                out[i] = nv;
                ch |= (nv ^ cv[i]);
            }
            uint4* op = (uint4*)(nxt + r * WPR);
            op[0] = make_uint4(out[0], out[1], out[2], out[3]);
            op[1] = make_uint4(out[4], out[5], out[6], out[7]);
            op[2] = make_uint4(out[8], out[9], out[10], out[11]);
            op[3] = make_uint4(out[12], out[13], out[14], out[15]);
            changed |= (int)(ch != 0u);
        }
        int any = __syncthreads_or(changed);
        uint32_t* tsw = cur; cur = nxt; nxt = tsw;
        if (!any) break;   // fixed point: identical to reference while_loop result
    }
    for (int i = tid; i < WORDS_PER_IMG; i += 256) g_edges[base + i] = cur[i];
}

// ---------------- XOR popcount reduction + sqrt ---------------------------
__global__ __launch_bounds__(256) void k_diff() {
    const int total = BATCH * WORDS_PER_IMG;          // words per image-set
    int idx = blockIdx.x * blockDim.x + threadIdx.x;
    int stride = gridDim.x * blockDim.x;
    int sum = 0;
    for (int i = idx; i < total; i += stride)
        sum += __popc(g_edges[i] ^ g_edges[total + i]);
#pragma unroll
    for (int o = 16; o > 0; o >>= 1) sum += __shfl_down_sync(0xffffffffu, sum, o);
    __shared__ int wsum[8];
    int lane = threadIdx.x & 31, w = threadIdx.x >> 5;
    if (lane == 0) wsum[w] = sum;
    __syncthreads();
    if (threadIdx.x == 0) {
        int s2 = 0;
#pragma unroll
        for (int i = 0; i < 8; i++) s2 += wsum[i];
        atomicAdd(&g_count, (unsigned)s2);
    }
}

__global__ void k_final(float* out, int n) {
    float v = sqrtf((float)g_count);
    for (int i = threadIdx.x; i < n; i += blockDim.x) out[i] = v;
}

// ---------------- launch ---------------------------------------------------
extern "C" void kernel_launch(void* const* d_in, const int* in_sizes, int n_in,
                              void* d_out, int out_size) {
    const float* A = (const float*)d_in[0];
    const float* B = (const float*)d_in[1];

    size_t smemF = (size_t)(GRAY_ROWS * WW + MAG_ROWS * MAG_PITCH) * sizeof(__half); // ~71.8KB
    size_t smemH = (size_t)4 * WORDS_PER_IMG * sizeof(uint32_t);                      // 128KB

    cudaFuncSetAttribute(k_frontend, cudaFuncAttributeMaxDynamicSharedMemorySize, (int)smemF);
    cudaFuncSetAttribute(k_hyster,   cudaFuncAttributeMaxDynamicSharedMemorySize, (int)smemH);

    k_init<<<1, 1>>>();
    k_frontend<<<dim3(HH / TILE_H, BATCH, 2), 256, smemF>>>(A, B);
    k_hyster<<<2 * BATCH, 256, smemH>>>();
    k_diff<<<128, 256>>>();
    k_final<<<1, 32>>>((float*)d_out, out_size);
}